// round 14
// baseline (speedup 1.0000x reference)
#include <cuda_runtime.h>
#include <cuda_bf16.h>
#include <cstdint>

// Problem constants
#define HIDDEN 2048
#define INTER  1408
#define NEXP   60
#define TOPK   6

// Scratch (no cudaMalloc allowed)
__device__ __align__(16) float g_inter[TOPK * INTER]; // weighted silu(gate)*up

// ---------------------------------------------------------------------------
// Warp-local expert resolve: no shared memory, no __syncthreads.
// Lane l (<6) inspects idx[l]; ballot decides int64 vs int32; shfl broadcasts.
// ---------------------------------------------------------------------------
__device__ __forceinline__ int warp_expert(const void* idx_raw, int k, int lane) {
    const long long* p64 = (const long long*)idx_raw;
    const int*       p32 = (const int*)idx_raw;
    long long v64 = 0; int v32 = 0;
    if (lane < TOPK) { v64 = __ldg(p64 + lane); v32 = __ldg(p32 + lane); }
    unsigned good = __ballot_sync(0xffffffffu, lane < TOPK && v64 >= 0 && v64 < NEXP);
    bool ok64 = (good & 0x3Fu) == 0x3Fu;
    int e = ok64 ? (int)v64 : v32;
    return __shfl_sync(0xffffffffu, e, k);
}

// ---------------------------------------------------------------------------
// Kernel 1: warp per (k,i):
//   g = dot(gate_row, x), u = dot(up_row, x)
//   g_inter[k*INTER+i] = silu(g) * u * topk_weights[k]
// 2112 blocks x 128 thr; x via __ldg (8KB, L1-resident). Block 0 zeroes out.
// Achieves ~5.7 TB/s — near practical ceiling; unchanged.
// ---------------------------------------------------------------------------
__global__ __launch_bounds__(128) void gateup_kernel(
    const float* __restrict__ x,
    const void*  __restrict__ idx_raw,
    const float* __restrict__ topk_w,
    const float* __restrict__ gate_up_all,
    float* __restrict__ out)
{
    int warp  = threadIdx.x >> 5;
    int lane  = threadIdx.x & 31;
    int gwarp = blockIdx.x * 4 + warp;

    // Block 0 zeroes the output (down_kernel accumulates with atomics)
    if (blockIdx.x == 0) {
#pragma unroll
        for (int t = 0; t < HIDDEN / 128; t++)
            out[t * 128 + threadIdx.x] = 0.f;
    }

    if (gwarp >= TOPK * INTER) return;

    int k = gwarp / INTER;
    int i = gwarp - k * INTER;
    int e = warp_expert(idx_raw, k, lane);

    const float4* xv4  = (const float4*)x;
    const float4* grow = (const float4*)(gate_up_all + ((size_t)e * (2 * INTER) + i) * HIDDEN);
    const float4* urow = (const float4*)(gate_up_all + ((size_t)e * (2 * INTER) + INTER + i) * HIDDEN);

    float dg = 0.f, du = 0.f;
#pragma unroll
    for (int t = 0; t < HIDDEN / 128; t++) {      // 16 iterations
        int idx = t * 32 + lane;
        float4 xv = __ldg (xv4  + idx);           // L1-hot
        float4 gv = __ldcs(grow + idx);           // stream-once
        float4 uv = __ldcs(urow + idx);
        dg += xv.x * gv.x + xv.y * gv.y + xv.z * gv.z + xv.w * gv.w;
        du += xv.x * uv.x + xv.y * uv.y + xv.z * uv.z + xv.w * uv.w;
    }
#pragma unroll
    for (int o = 16; o; o >>= 1) {
        dg += __shfl_xor_sync(0xffffffffu, dg, o);
        du += __shfl_xor_sync(0xffffffffu, du, o);
    }
    if (lane == 0) {
        float s = dg / (1.f + __expf(-dg));        // silu
        g_inter[gwarp] = s * du * __ldg(topk_w + k);
    }
}

// ---------------------------------------------------------------------------
// Kernel 2: warp per (k, h-pair, half): two contiguous rows h0,h0+1 of
// expert k, half the iterations each (half0: t=0..5, half1: t=6..10).
// 12288 warps. KEY CHANGE vs R12: __launch_bounds__(128, 14) caps regs at
// ~36 -> 56 resident warps/SM (was 44 @ regs=46); #pragma unroll 3 stops
// ptxas from batching 6 iterations into registers. Resident-warps x
// per-warp-MLP is the DRAM concurrency budget; this raises the warp factor.
// ---------------------------------------------------------------------------
__global__ __launch_bounds__(128, 14) void down_kernel(
    const void*  __restrict__ idx_raw,
    const float* __restrict__ down_all,
    float* __restrict__ out)
{
    int warp  = threadIdx.x >> 5;
    int lane  = threadIdx.x & 31;
    int gwarp = blockIdx.x * 4 + warp;        // 0 .. 12287
    if (gwarp >= TOPK * HIDDEN) return;

    int pair = gwarp >> 1;
    int half = gwarp & 1;
    int k    = pair >> 10;                    // / (HIDDEN/2)
    int h0   = (pair & (HIDDEN / 2 - 1)) << 1;
    int e    = warp_expert(idx_raw, k, lane);

    const float4* row0 = (const float4*)(down_all + ((size_t)e * HIDDEN + h0) * INTER);
    const float4* row1 = row0 + INTER / 4;    // contiguous next row
    const float4* iv   = (const float4*)(g_inter + k * INTER);

    // half0: t = 0..5 (6 iters), half1: t = 6..10 (5 iters)
    int t0 = half * 6;
    int t1 = 6 + half * 5;

    float acc0 = 0.f, acc1 = 0.f;
#pragma unroll 3
    for (int t = t0; t < t1; t++) {
        int idx = t * 32 + lane;
        float4 a0 = __ldcs(row0 + idx);       // DRAM stream 0
        float4 a1 = __ldcs(row1 + idx);       // DRAM stream 1
        float4 b  = __ldg (iv   + idx);       // L1/L2-hot
        acc0 += a0.x * b.x + a0.y * b.y + a0.z * b.z + a0.w * b.w;
        acc1 += a1.x * b.x + a1.y * b.y + a1.z * b.z + a1.w * b.w;
    }
#pragma unroll
    for (int o = 16; o; o >>= 1) {
        acc0 += __shfl_xor_sync(0xffffffffu, acc0, o);
        acc1 += __shfl_xor_sync(0xffffffffu, acc1, o);
    }
    if (lane == 0) {
        atomicAdd(out + h0,     acc0);
        atomicAdd(out + h0 + 1, acc1);
    }
}

// ---------------------------------------------------------------------------
// Inputs (metadata order):
//   0: x_bc1t        float32 [2048]
//   1: topk_idx      int64   [6]
//   2: topk_weights  float32 [6]
//   3: gate_up_all   float32 [60, 2816, 2048]
//   4: down_all      float32 [60, 2048, 1408]
// Output: float32 [2048]
// ---------------------------------------------------------------------------
extern "C" void kernel_launch(void* const* d_in, const int* in_sizes, int n_in,
                              void* d_out, int out_size) {
    const float* x    = (const float*)d_in[0];
    const void*  idx  = d_in[1];
    const float* w    = (const float*)d_in[2];
    const float* gu   = (const float*)d_in[3];
    const float* down = (const float*)d_in[4];
    float*       out  = (float*)d_out;

    int blocks1 = (TOPK * INTER + 3) / 4;        // 2112 blocks x 128 thr
    gateup_kernel<<<blocks1, 128>>>(x, idx, w, gu, out);

    int blocks2 = (TOPK * HIDDEN + 3) / 4;       // 3072 blocks x 128 thr
    down_kernel<<<blocks2, 128>>>(idx, down, out);
}